// round 13
// baseline (speedup 1.0000x reference)
#include <cuda_runtime.h>
#include <cstdint>

#define IN_DIM 1433
#define HID 16
#define OUTD 7
#define MAXN 200000
#define MAXE 6400000
#define MAXNB 256

// gemm1 mma.sync tiling
#define KP 1448                  // B smem pitch (bf16) -> 724 words, conflict-free
#define KPW (KP / 2)
#define SMEM_BHALF (16 * KP * 2)             // 46336
#define SMEM_B_BYTES (2 * SMEM_BHALF)        // 92672
#define NCHUNK 45                             // 45*32 = 1440 >= 1433
#define CHUNKK 32
#define AP 20                                 // A pitch in u32 words: (20g+q)%32 distinct
#define ABUF_WORDS (256 * AP)                 // 5120 words per buffer
#define SMEM_A_BYTES (4 * ABUF_WORDS * 4)     // hi/lo x double-buffer = 81920
#define SMEM_TOTAL (SMEM_B_BYTES + SMEM_A_BYTES)   // 174592

// Scratch (__device__ globals; allocations are forbidden)
__device__ float g_xw1[(size_t)MAXN * HID];
__device__ float g_h[(size_t)MAXN * HID];
__device__ float g_g[(size_t)MAXN * 8];
__device__ int2  g_csr[(size_t)MAXE];
__device__ int   g_rowcnt[MAXN];
__device__ int   g_rowfill[MAXN];
__device__ int   g_rowptr[MAXN + 1];
__device__ int   g_blocksum[MAXNB];
__device__ int   g_blockoff[MAXNB];
__device__ int   g_idx64;

// ---------------------------------------------------------------------------
__device__ __forceinline__ void split2(float x0, float x1, uint32_t& hi, uint32_t& lo)
{
    uint32_t u0 = __float_as_uint(x0) & 0xFFFF0000u;
    uint32_t u1 = __float_as_uint(x1) & 0xFFFF0000u;
    hi = __byte_perm(u0, u1, 0x7632);
    float l0 = x0 - __uint_as_float(u0);
    float l1 = x1 - __uint_as_float(u1);
    asm("cvt.rn.bf16x2.f32 %0, %1, %2;" : "=r"(lo) : "f"(l1), "f"(l0));
}

__device__ __forceinline__ void mma16816(float& d0, float& d1, float& d2, float& d3,
                                         uint32_t a0, uint32_t a1, uint32_t a2, uint32_t a3,
                                         uint32_t b0, uint32_t b1)
{
    asm volatile(
        "mma.sync.aligned.m16n8k16.row.col.f32.bf16.bf16.f32 "
        "{%0,%1,%2,%3}, {%4,%5,%6,%7}, {%8,%9}, {%0,%1,%2,%3};"
        : "+f"(d0), "+f"(d1), "+f"(d2), "+f"(d3)
        : "r"(a0), "r"(a1), "r"(a2), "r"(a3), "r"(b0), "r"(b1));
}

// ---------------------------------------------------------------------------
__global__ void detect_idx_kernel(const unsigned int* __restrict__ adj_words, int n_edges)
{
    int i = threadIdx.x;
    int samples = n_edges < 1024 ? n_edges : 1024;
    int ok = 1;
    if (i < samples) ok = (adj_words[2 * i + 1] == 0u) ? 1 : 0;
    int all = __syncthreads_and(ok);
    if (i == 0) g_idx64 = all;
}

__device__ __forceinline__ int load_row(const void* adj, int e, int is64) {
    return is64 ? (int)__ldg((const long long*)adj + e)
                : __ldg((const int*)adj + e);
}
__device__ __forceinline__ int load_col(const void* adj, int e, int n_edges, int is64) {
    return is64 ? (int)__ldg((const long long*)adj + (size_t)n_edges + e)
                : __ldg((const int*)adj + (size_t)n_edges + e);
}

// ---------------------------------------------------------------------------
__global__ void zero_counts_kernel(int n)
{
    int i = blockIdx.x * blockDim.x + threadIdx.x;
    if (i < n) { g_rowcnt[i] = 0; g_rowfill[i] = 0; }
}

__global__ __launch_bounds__(256) void histogram_kernel(
    const void* __restrict__ adj, int n_edges)
{
    int e = blockIdx.x * blockDim.x + threadIdx.x;
    if (e >= n_edges) return;
    int r = load_row(adj, e, g_idx64);
    atomicAdd(&g_rowcnt[r], 1);
}

__device__ __forceinline__ int block_excl_scan(int v, int* warp_sums, int nwarps)
{
    const int lane = threadIdx.x & 31, w = threadIdx.x >> 5;
    int x = v;
    #pragma unroll
    for (int off = 1; off < 32; off <<= 1) {
        int y = __shfl_up_sync(0xffffffffu, x, off);
        if (lane >= off) x += y;
    }
    if (lane == 31) warp_sums[w] = x;
    __syncthreads();
    if (w == 0) {
        int s = (lane < nwarps) ? warp_sums[lane] : 0;
        #pragma unroll
        for (int off = 1; off < 32; off <<= 1) {
            int y = __shfl_up_sync(0xffffffffu, s, off);
            if (lane >= off) s += y;
        }
        if (lane < nwarps) warp_sums[lane] = s;
    }
    __syncthreads();
    int base = (w > 0) ? warp_sums[w - 1] : 0;
    return base + x - v;
}

__global__ __launch_bounds__(1024) void scan1_kernel(int n)
{
    __shared__ int ws[32];
    int i = blockIdx.x * 1024 + threadIdx.x;
    int v = (i < n) ? g_rowcnt[i] : 0;
    int ex = block_excl_scan(v, ws, 32);
    if (threadIdx.x == 1023) g_blocksum[blockIdx.x] = ex + v;
}

__global__ __launch_bounds__(256) void scan2_kernel(int nb)
{
    __shared__ int ws[32];
    int i = threadIdx.x;
    int v = (i < nb) ? g_blocksum[i] : 0;
    int ex = block_excl_scan(v, ws, 8);
    if (i < nb) g_blockoff[i] = ex;
}

__global__ __launch_bounds__(1024) void scan3_kernel(int n)
{
    __shared__ int ws[32];
    int i = blockIdx.x * 1024 + threadIdx.x;
    int v = (i < n) ? g_rowcnt[i] : 0;
    int ex = block_excl_scan(v, ws, 32);
    int base = g_blockoff[blockIdx.x];
    if (i < n)      g_rowptr[i] = base + ex;
    if (i == n - 1) g_rowptr[n] = base + ex + v;
}

__global__ __launch_bounds__(256) void scatter_kernel(
    const void* __restrict__ adj, const float* __restrict__ vals, int n_edges)
{
    int e = blockIdx.x * blockDim.x + threadIdx.x;
    if (e >= n_edges) return;
    const int is64 = g_idx64;
    int r = load_row(adj, e, is64);
    int c = load_col(adj, e, n_edges, is64);
    float v = __ldg(vals + e);
    int pos = g_rowptr[r] + atomicAdd(&g_rowfill[r], 1);
    g_csr[pos] = make_int2(c, __float_as_int(v));
}

// ---------------------------------------------------------------------------
// GEMM1 via mma.sync bf16 split (hh + hl + lh).
// A is split fp32 -> (hi, lo) bf16x2 ONCE at staging time and stored in smem
// word buffers; the hot loop is pure LDS.32 fragment loads + MMAs.
// 1024 threads = 32 warps; warps w and w+16 share 16 A-rows, each owns one
// n8 half. One __syncthreads per 32-k chunk, double-buffered.
__global__ __launch_bounds__(1024) void gemm1_mma_kernel(
    const float* __restrict__ feature,
    const float* __restrict__ W1,
    int n_nodes, int ntiles256)
{
    extern __shared__ char smem[];
    uint32_t* shi  = (uint32_t*)smem;
    uint32_t* slo  = (uint32_t*)(smem + SMEM_BHALF);
    uint32_t* sAhi = (uint32_t*)(smem + SMEM_B_BYTES);                      // [2][ABUF_WORDS]
    uint32_t* sAlo = (uint32_t*)(smem + SMEM_B_BYTES + 2 * ABUF_WORDS * 4); // [2][ABUF_WORDS]

    const int tid  = threadIdx.x;
    const int warp = tid >> 5;
    const int lane = tid & 31;
    const int g    = lane >> 2;
    const int q    = lane & 3;
    const int q2   = q * 2;
    const int h    = warp >> 4;          // n8 half owned by this warp
    const int wrow = warp & 15;          // A row-group

    // stage W1^T split (zero-padded to KP)
    for (int idx = tid; idx < 16 * KPW; idx += 1024) {
        int n  = idx / KPW;
        int kp = idx - n * KPW;
        int k  = kp * 2;
        float w0 = (k     < IN_DIM) ? __ldg(W1 + (size_t)k       * HID + n) : 0.0f;
        float w1 = (k + 1 < IN_DIM) ? __ldg(W1 + (size_t)(k + 1) * HID + n) : 0.0f;
        uint32_t hi, lo;
        split2(w0, w1, hi, lo);
        shi[n * KPW + kp] = hi;
        slo[n * KPW + kp] = lo;
    }
    __syncthreads();

    const int bw    = (h * 8 + g) * KPW + q;
    const int srow0 = wrow * 16 + g;

    for (int t = blockIdx.x; t < ntiles256; t += gridDim.x) {
        const int row0 = t * 256;

        float d0 = 0.f, d1 = 0.f, d2 = 0.f, d3 = 0.f;
        uint32_t sth[4], stl[4];

        // prologue: stage chunk 0 (each thread: 4 word-pairs = 8 fp32)
        #pragma unroll
        for (int i = 0; i < 4; i++) {
            const int w   = tid + i * 1024;       // word id in chunk (0..4095)
            const int r   = w >> 4;               // row 0..255
            const int wc  = w & 15;               // word col 0..15
            const int col = wc * 2;
            const int gr  = row0 + r;
            float f0 = 0.f, f1 = 0.f;
            if (gr < n_nodes) {
                const float* fp = feature + (size_t)gr * IN_DIM;
                if (col     < IN_DIM) f0 = __ldg(fp + col);
                if (col + 1 < IN_DIM) f1 = __ldg(fp + col + 1);
            }
            split2(f0, f1, sth[i], stl[i]);
        }
        #pragma unroll
        for (int i = 0; i < 4; i++) {
            const int w = tid + i * 1024;
            const int a = (w >> 4) * AP + (w & 15);
            sAhi[a] = sth[i];
            sAlo[a] = stl[i];
        }

        #pragma unroll 1
        for (int c = 0; c < NCHUNK; c++) {
            __syncthreads();   // publish chunk c; retire readers of chunk c-1

            // LDG + split chunk c+1 into registers (overlaps compute below)
            if (c + 1 < NCHUNK) {
                const int kc = (c + 1) * CHUNKK;
                #pragma unroll
                for (int i = 0; i < 4; i++) {
                    const int w   = tid + i * 1024;
                    const int r   = w >> 4;
                    const int col = kc + (w & 15) * 2;
                    const int gr  = row0 + r;
                    float f0 = 0.f, f1 = 0.f;
                    if (gr < n_nodes) {
                        const float* fp = feature + (size_t)gr * IN_DIM;
                        if (col     < IN_DIM) f0 = __ldg(fp + col);
                        if (col + 1 < IN_DIM) f1 = __ldg(fp + col + 1);
                    }
                    split2(f0, f1, sth[i], stl[i]);
                }
            }

            // compute chunk c from buffer c&1 (pure LDS + MMA)
            {
                const uint32_t* bh = sAhi + (c & 1) * ABUF_WORDS;
                const uint32_t* bl = sAlo + (c & 1) * ABUF_WORDS;
                const int ra0 = srow0 * AP;
                const int ra1 = (srow0 + 8) * AP;
                #pragma unroll
                for (int ks = 0; ks < 2; ks++) {
                    const int wc = ks * 8 + q;
                    const uint32_t a0h = bh[ra0 + wc],     a0l = bl[ra0 + wc];
                    const uint32_t a2h = bh[ra0 + wc + 4], a2l = bl[ra0 + wc + 4];
                    const uint32_t a1h = bh[ra1 + wc],     a1l = bl[ra1 + wc];
                    const uint32_t a3h = bh[ra1 + wc + 4], a3l = bl[ra1 + wc + 4];

                    const int base = bw + c * (CHUNKK / 2) + ks * 8;
                    const uint32_t b0h = shi[base], b1h = shi[base + 4];
                    const uint32_t b0l = slo[base], b1l = slo[base + 4];
                    mma16816(d0, d1, d2, d3, a0h, a1h, a2h, a3h, b0h, b1h);
                    mma16816(d0, d1, d2, d3, a0h, a1h, a2h, a3h, b0l, b1l);
                    mma16816(d0, d1, d2, d3, a0l, a1l, a2l, a3l, b0h, b1h);
                }
            }

            // STS chunk c+1 into the other buffer
            if (c + 1 < NCHUNK) {
                uint32_t* nh = sAhi + ((c + 1) & 1) * ABUF_WORDS;
                uint32_t* nl = sAlo + ((c + 1) & 1) * ABUF_WORDS;
                #pragma unroll
                for (int i = 0; i < 4; i++) {
                    const int w = tid + i * 1024;
                    const int a = (w >> 4) * AP + (w & 15);
                    nh[a] = sth[i];
                    nl[a] = stl[i];
                }
            }
        }

        // store D (each warp owns an 8-col half of its 16 rows)
        const int rg0 = row0 + srow0;
        const int rg1 = rg0 + 8;
        if (rg0 < n_nodes)
            *(float2*)(g_xw1 + (size_t)rg0 * HID + h * 8 + q2) = make_float2(d0, d1);
        if (rg1 < n_nodes)
            *(float2*)(g_xw1 + (size_t)rg1 * HID + h * 8 + q2) = make_float2(d2, d3);

        __syncthreads();   // all reads of buffers done before next tile's prologue
    }
}

// ---------------------------------------------------------------------------
__global__ __launch_bounds__(256) void spmm1_gather_kernel(int n_nodes)
{
    const int warp_id = (blockIdx.x * blockDim.x + threadIdx.x) >> 5;
    if (warp_id >= n_nodes) return;
    const int lane = threadIdx.x & 31;
    const int g  = lane >> 2;
    const int j4 = lane & 3;

    const int start = g_rowptr[warp_id];
    const int end   = g_rowptr[warp_id + 1];

    float4 acc = make_float4(0.f, 0.f, 0.f, 0.f);
    for (int e = start + g; e < end; e += 8) {
        const int2 ev = __ldg(&g_csr[e]);
        const float v = __int_as_float(ev.y);
        const float4 x = __ldg((const float4*)(g_xw1 + (size_t)ev.x * HID) + j4);
        acc.x += v * x.x; acc.y += v * x.y; acc.z += v * x.z; acc.w += v * x.w;
    }
    #pragma unroll
    for (int off = 16; off >= 4; off >>= 1) {
        acc.x += __shfl_xor_sync(0xffffffffu, acc.x, off);
        acc.y += __shfl_xor_sync(0xffffffffu, acc.y, off);
        acc.z += __shfl_xor_sync(0xffffffffu, acc.z, off);
        acc.w += __shfl_xor_sync(0xffffffffu, acc.w, off);
    }
    if (g == 0)
        ((float4*)(g_h + (size_t)warp_id * HID))[j4] = acc;
}

// ---------------------------------------------------------------------------
__global__ __launch_bounds__(256) void gemm2_kernel(
    const float* __restrict__ b1,
    const float* __restrict__ W2,
    int n_nodes)
{
    __shared__ float sW2[HID * OUTD];
    __shared__ float sb1[HID];
    if (threadIdx.x < HID * OUTD) sW2[threadIdx.x] = W2[threadIdx.x];
    if (threadIdx.x < HID)        sb1[threadIdx.x] = b1[threadIdx.x];
    __syncthreads();

    int i = blockIdx.x * blockDim.x + threadIdx.x;
    if (i >= n_nodes) return;

    float h[HID];
    const float4* hp = (const float4*)(g_h + (size_t)i * HID);
    #pragma unroll
    for (int q = 0; q < 4; q++) {
        float4 a = hp[q];
        h[4 * q + 0] = a.x; h[4 * q + 1] = a.y;
        h[4 * q + 2] = a.z; h[4 * q + 3] = a.w;
    }

    float o[OUTD];
    #pragma unroll
    for (int j = 0; j < OUTD; j++) o[j] = 0.0f;
    #pragma unroll
    for (int k = 0; k < HID; k++) {
        const float hv = fmaxf(h[k] + sb1[k], 0.0f);
        #pragma unroll
        for (int j = 0; j < OUTD; j++) o[j] += hv * sW2[k * OUTD + j];
    }

    float4* gp = (float4*)(g_g + (size_t)i * 8);
    gp[0] = make_float4(o[0], o[1], o[2], o[3]);
    gp[1] = make_float4(o[4], o[5], o[6], 0.0f);
}

// ---------------------------------------------------------------------------
__global__ __launch_bounds__(256) void spmm2_gather_kernel(
    float* __restrict__ out, const float* __restrict__ b2, int n_nodes)
{
    const int warp_id = (blockIdx.x * blockDim.x + threadIdx.x) >> 5;
    if (warp_id >= n_nodes) return;
    const int lane = threadIdx.x & 31;
    const int g  = lane >> 1;
    const int j4 = lane & 1;

    const int start = g_rowptr[warp_id];
    const int end   = g_rowptr[warp_id + 1];

    float4 acc = make_float4(0.f, 0.f, 0.f, 0.f);
    for (int e = start + g; e < end; e += 16) {
        const int2 ev = __ldg(&g_csr[e]);
        const float v = __int_as_float(ev.y);
        const float4 x = __ldg((const float4*)(g_g + (size_t)ev.x * 8) + j4);
        acc.x += v * x.x; acc.y += v * x.y; acc.z += v * x.z; acc.w += v * x.w;
    }
    #pragma unroll
    for (int off = 16; off >= 2; off >>= 1) {
        acc.x += __shfl_xor_sync(0xffffffffu, acc.x, off);
        acc.y += __shfl_xor_sync(0xffffffffu, acc.y, off);
        acc.z += __shfl_xor_sync(0xffffffffu, acc.z, off);
        acc.w += __shfl_xor_sync(0xffffffffu, acc.w, off);
    }
    float* o = out + (size_t)warp_id * OUTD;
    if (lane == 0) {
        o[0] = acc.x + __ldg(b2 + 0);
        o[1] = acc.y + __ldg(b2 + 1);
        o[2] = acc.z + __ldg(b2 + 2);
        o[3] = acc.w + __ldg(b2 + 3);
    } else if (lane == 1) {
        o[4] = acc.x + __ldg(b2 + 4);
        o[5] = acc.y + __ldg(b2 + 5);
        o[6] = acc.z + __ldg(b2 + 6);
    }
}

// ---------------------------------------------------------------------------
extern "C" void kernel_launch(void* const* d_in, const int* in_sizes, int n_in,
                              void* d_out, int out_size)
{
    const void*  adj     = d_in[0];
    const float* vals    = (const float*)d_in[1];
    const float* feature = (const float*)d_in[2];
    const float* W1      = (const float*)d_in[3];
    const float* b1      = (const float*)d_in[4];
    const float* W2      = (const float*)d_in[5];
    const float* b2      = (const float*)d_in[6];
    float*       out     = (float*)d_out;

    const int n_edges   = in_sizes[1];
    const int n_nodes   = in_sizes[2] / IN_DIM;
    const int ntiles256 = (n_nodes + 255) / 256;
    const int nb        = (n_nodes + 1023) / 1024;

    static cudaStream_t s2 = nullptr;
    static cudaEvent_t ev_fork = nullptr, ev_join = nullptr;
    static int n_sms = 148;
    if (!s2) {
        cudaFuncSetAttribute(gemm1_mma_kernel,
                             cudaFuncAttributeMaxDynamicSharedMemorySize, SMEM_TOTAL);
        cudaStreamCreateWithFlags(&s2, cudaStreamNonBlocking);
        cudaEventCreateWithFlags(&ev_fork, cudaEventDisableTiming);
        cudaEventCreateWithFlags(&ev_join, cudaEventDisableTiming);
        int dev = 0;
        cudaGetDevice(&dev);
        cudaDeviceGetAttribute(&n_sms, cudaDevAttrMultiProcessorCount, dev);
    }

    cudaEventRecord(ev_fork, 0);
    cudaStreamWaitEvent(s2, ev_fork, 0);

    // CSR chain on side stream; gemm1 stays the 4th launch (profiled slot).
    detect_idx_kernel<<<1, 1024, 0, s2>>>((const unsigned int*)adj, n_edges);
    zero_counts_kernel<<<nb, 1024, 0, s2>>>(n_nodes);
    histogram_kernel<<<(n_edges + 255) / 256, 256, 0, s2>>>(adj, n_edges);

    gemm1_mma_kernel<<<n_sms, 1024, SMEM_TOTAL>>>(feature, W1, n_nodes, ntiles256);

    scan1_kernel<<<nb, 1024, 0, s2>>>(n_nodes);
    scan2_kernel<<<1, 256, 0, s2>>>(nb);
    scan3_kernel<<<nb, 1024, 0, s2>>>(n_nodes);
    scatter_kernel<<<(n_edges + 255) / 256, 256, 0, s2>>>(adj, vals, n_edges);
    cudaEventRecord(ev_join, s2);

    cudaStreamWaitEvent(0, ev_join, 0);
    spmm1_gather_kernel<<<(n_nodes * 32 + 255) / 256, 256>>>(n_nodes);
    gemm2_kernel<<<(n_nodes + 255) / 256, 256>>>(b1, W2, n_nodes);
    spmm2_gather_kernel<<<(n_nodes * 32 + 255) / 256, 256>>>(out, b2, n_nodes);
}

// round 14
// speedup vs baseline: 1.1680x; 1.1680x over previous
#include <cuda_runtime.h>
#include <cstdint>

#define IN_DIM 1433
#define HID 16
#define OUTD 7
#define MAXN 200000
#define MAXE 6400000
#define MAXNB 256

// gemm1 mma.sync tiling
#define NCHUNK 45                 // 45*32 = 1440 >= 1433 (zero-padded)
#define CHUNKK 32
#define NKS    (NCHUNK * 2)       // 90 global k-steps of 16
#define PB 1456                   // B row pitch (u32 words); 1456%32=16 -> LDS.128 conflict-free
#define PA 48                     // A row pitch (u32 words); 48%32=16 -> LDS.128 conflict-free
#define SMEM_B_BYTES (16 * PB * 4)            // 93184 (hi/lo interleaved)
#define ABUF_WORDS (256 * PA)                 // 12288 words per buffer
#define SMEM_A_BYTES (2 * ABUF_WORDS * 4)     // 98304 (double buffered)
#define SMEM_TOTAL (SMEM_B_BYTES + SMEM_A_BYTES)   // 191488

// Scratch (__device__ globals; allocations are forbidden)
__device__ float g_xw1[(size_t)MAXN * HID];
__device__ float g_h[(size_t)MAXN * HID];
__device__ float g_g[(size_t)MAXN * 8];
__device__ int2  g_csr[(size_t)MAXE];
__device__ int   g_rowcnt[MAXN];
__device__ int   g_rowfill[MAXN];
__device__ int   g_rowptr[MAXN + 1];
__device__ int   g_blocksum[MAXNB];
__device__ int   g_blockoff[MAXNB];
__device__ int   g_idx64;

// ---------------------------------------------------------------------------
__device__ __forceinline__ void split2(float x0, float x1, uint32_t& hi, uint32_t& lo)
{
    uint32_t u0 = __float_as_uint(x0) & 0xFFFF0000u;
    uint32_t u1 = __float_as_uint(x1) & 0xFFFF0000u;
    hi = __byte_perm(u0, u1, 0x7632);
    float l0 = x0 - __uint_as_float(u0);
    float l1 = x1 - __uint_as_float(u1);
    asm("cvt.rn.bf16x2.f32 %0, %1, %2;" : "=r"(lo) : "f"(l1), "f"(l0));
}

__device__ __forceinline__ void mma16816(float& d0, float& d1, float& d2, float& d3,
                                         uint32_t a0, uint32_t a1, uint32_t a2, uint32_t a3,
                                         uint32_t b0, uint32_t b1)
{
    asm volatile(
        "mma.sync.aligned.m16n8k16.row.col.f32.bf16.bf16.f32 "
        "{%0,%1,%2,%3}, {%4,%5,%6,%7}, {%8,%9}, {%0,%1,%2,%3};"
        : "+f"(d0), "+f"(d1), "+f"(d2), "+f"(d3)
        : "r"(a0), "r"(a1), "r"(a2), "r"(a3), "r"(b0), "r"(b1));
}

// word w (0..15 within a 32-col chunk row) -> interleaved fragment position
// group: [hi_{8ks+q}, hi_{8ks+q+4}, lo_{8ks+q}, lo_{8ks+q+4}] at 16ks+4q
__device__ __forceinline__ int frag_pos(int w)
{
    return ((w >> 3) << 4) + ((w & 3) << 2) + ((w >> 2) & 1);
}

// ---------------------------------------------------------------------------
__global__ void detect_idx_kernel(const unsigned int* __restrict__ adj_words, int n_edges)
{
    int i = threadIdx.x;
    int samples = n_edges < 1024 ? n_edges : 1024;
    int ok = 1;
    if (i < samples) ok = (adj_words[2 * i + 1] == 0u) ? 1 : 0;
    int all = __syncthreads_and(ok);
    if (i == 0) g_idx64 = all;
}

__device__ __forceinline__ int load_row(const void* adj, int e, int is64) {
    return is64 ? (int)__ldg((const long long*)adj + e)
                : __ldg((const int*)adj + e);
}
__device__ __forceinline__ int load_col(const void* adj, int e, int n_edges, int is64) {
    return is64 ? (int)__ldg((const long long*)adj + (size_t)n_edges + e)
                : __ldg((const int*)adj + (size_t)n_edges + e);
}

// ---------------------------------------------------------------------------
__global__ void zero_counts_kernel(int n)
{
    int i = blockIdx.x * blockDim.x + threadIdx.x;
    if (i < n) { g_rowcnt[i] = 0; g_rowfill[i] = 0; }
}

__global__ __launch_bounds__(256) void histogram_kernel(
    const void* __restrict__ adj, int n_edges)
{
    int e = blockIdx.x * blockDim.x + threadIdx.x;
    if (e >= n_edges) return;
    int r = load_row(adj, e, g_idx64);
    atomicAdd(&g_rowcnt[r], 1);
}

__device__ __forceinline__ int block_excl_scan(int v, int* warp_sums, int nwarps)
{
    const int lane = threadIdx.x & 31, w = threadIdx.x >> 5;
    int x = v;
    #pragma unroll
    for (int off = 1; off < 32; off <<= 1) {
        int y = __shfl_up_sync(0xffffffffu, x, off);
        if (lane >= off) x += y;
    }
    if (lane == 31) warp_sums[w] = x;
    __syncthreads();
    if (w == 0) {
        int s = (lane < nwarps) ? warp_sums[lane] : 0;
        #pragma unroll
        for (int off = 1; off < 32; off <<= 1) {
            int y = __shfl_up_sync(0xffffffffu, s, off);
            if (lane >= off) s += y;
        }
        if (lane < nwarps) warp_sums[lane] = s;
    }
    __syncthreads();
    int base = (w > 0) ? warp_sums[w - 1] : 0;
    return base + x - v;
}

__global__ __launch_bounds__(1024) void scan1_kernel(int n)
{
    __shared__ int ws[32];
    int i = blockIdx.x * 1024 + threadIdx.x;
    int v = (i < n) ? g_rowcnt[i] : 0;
    int ex = block_excl_scan(v, ws, 32);
    if (threadIdx.x == 1023) g_blocksum[blockIdx.x] = ex + v;
}

__global__ __launch_bounds__(256) void scan2_kernel(int nb)
{
    __shared__ int ws[32];
    int i = threadIdx.x;
    int v = (i < nb) ? g_blocksum[i] : 0;
    int ex = block_excl_scan(v, ws, 8);
    if (i < nb) g_blockoff[i] = ex;
}

__global__ __launch_bounds__(1024) void scan3_kernel(int n)
{
    __shared__ int ws[32];
    int i = blockIdx.x * 1024 + threadIdx.x;
    int v = (i < n) ? g_rowcnt[i] : 0;
    int ex = block_excl_scan(v, ws, 32);
    int base = g_blockoff[blockIdx.x];
    if (i < n)      g_rowptr[i] = base + ex;
    if (i == n - 1) g_rowptr[n] = base + ex + v;
}

__global__ __launch_bounds__(256) void scatter_kernel(
    const void* __restrict__ adj, const float* __restrict__ vals, int n_edges)
{
    int e = blockIdx.x * blockDim.x + threadIdx.x;
    if (e >= n_edges) return;
    const int is64 = g_idx64;
    int r = load_row(adj, e, is64);
    int c = load_col(adj, e, n_edges, is64);
    float v = __ldg(vals + e);
    int pos = g_rowptr[r] + atomicAdd(&g_rowfill[r], 1);
    g_csr[pos] = make_int2(c, __float_as_int(v));
}

// ---------------------------------------------------------------------------
// GEMM1 via mma.sync bf16 split (hh + hl + lh).
// Staging keeps the coalesced stride-4B LDG pattern; adjacent lanes pair via
// shfl_xor(1) so the fp32->bf16 split happens ONCE at staging. A and B live
// in smem as interleaved fragment groups [hi_q, hi_{q+4}, lo_q, lo_{q+4}], so
// the hot loop is 3x LDS.128 + 3x MMA per warp-k-step (conflict-free pitches).
__global__ __launch_bounds__(1024) void gemm1_mma_kernel(
    const float* __restrict__ feature,
    const float* __restrict__ W1,
    int n_nodes, int ntiles256)
{
    extern __shared__ char smem[];
    uint32_t* sB = (uint32_t*)smem;                   // [16][PB]
    uint32_t* sA = (uint32_t*)(smem + SMEM_B_BYTES);  // [2][256][PA]

    const int tid  = threadIdx.x;
    const int warp = tid >> 5;
    const int lane = tid & 31;
    const int g    = lane >> 2;
    const int q    = lane & 3;
    const int q2   = q * 2;
    const int h    = warp >> 4;          // n8 half owned by this warp
    const int wrow = warp & 15;          // A row-group
    const bool even = (lane & 1) == 0;

    // stage W1^T split into interleaved fragment groups (zero-padded to 1440)
    for (int idx = tid; idx < 16 * (NKS * 8); idx += 1024) {
        const int n = idx / (NKS * 8);
        const int w = idx - n * (NKS * 8);       // word 0..719
        const int k = w * 2;
        float w0 = (k     < IN_DIM) ? __ldg(W1 + (size_t)k       * HID + n) : 0.0f;
        float w1 = (k + 1 < IN_DIM) ? __ldg(W1 + (size_t)(k + 1) * HID + n) : 0.0f;
        uint32_t hi, lo;
        split2(w0, w1, hi, lo);
        const int s  = w >> 3;                   // global k-step
        const int p  = n * PB + s * 16 + ((w & 3) << 2) + ((w >> 2) & 1);
        sB[p]     = hi;
        sB[p + 2] = lo;
    }
    __syncthreads();

    const int browbase = (h * 8 + g) * PB + q * 4;
    const int srow0 = wrow * 16 + g;

    for (int t = blockIdx.x; t < ntiles256; t += gridDim.x) {
        const int row0 = t * 256;

        float d0 = 0.f, d1 = 0.f, d2 = 0.f, d3 = 0.f;
        float f[8];

        // ---- prologue: LDG + shfl-split + STS chunk 0 ----
        #pragma unroll
        for (int i = 0; i < 8; i++) {
            const int idx = tid + i * 1024;
            const int r   = idx >> 5;
            const int col = idx & 31;
            const int gr  = row0 + r;
            f[i] = (gr < n_nodes && col < IN_DIM)
                 ? __ldg(feature + (size_t)gr * IN_DIM + col) : 0.0f;
        }
        #pragma unroll
        for (int i = 0; i < 8; i++) {
            const float x1 = __shfl_xor_sync(0xffffffffu, f[i], 1);
            if (even) {
                const int idx = tid + i * 1024;
                const int r   = idx >> 5;
                const int w   = (idx & 31) >> 1;
                uint32_t hi, lo;
                split2(f[i], x1, hi, lo);
                const int p = r * PA + frag_pos(w);
                sA[p]     = hi;
                sA[p + 2] = lo;
            }
        }

        #pragma unroll 1
        for (int c = 0; c < NCHUNK; c++) {
            __syncthreads();   // publish chunk c; retire readers of chunk c-1

            // LDG chunk c+1 (overlaps the compute below)
            if (c + 1 < NCHUNK) {
                const int kc = (c + 1) * CHUNKK;
                #pragma unroll
                for (int i = 0; i < 8; i++) {
                    const int idx = tid + i * 1024;
                    const int r   = idx >> 5;
                    const int col = kc + (idx & 31);
                    const int gr  = row0 + r;
                    f[i] = (gr < n_nodes && col < IN_DIM)
                         ? __ldg(feature + (size_t)gr * IN_DIM + col) : 0.0f;
                }
            }

            // compute chunk c: 3x LDS.128 + 3x MMA per k-step
            {
                const uint32_t* bufA = sA + (c & 1) * ABUF_WORDS;
                const int ra0 = srow0 * PA;
                const int ra1 = (srow0 + 8) * PA;
                #pragma unroll
                for (int ks = 0; ks < 2; ks++) {
                    const int ao = ks * 16 + q * 4;
                    const uint4 va0 = *(const uint4*)(bufA + ra0 + ao);
                    const uint4 va1 = *(const uint4*)(bufA + ra1 + ao);
                    const uint4 vb  = *(const uint4*)(sB + browbase + (c * 2 + ks) * 16);
                    // va = (a_h, a2_h, a_l, a2_l); vb = (b0h, b1h, b0l, b1l)
                    mma16816(d0, d1, d2, d3, va0.x, va1.x, va0.y, va1.y, vb.x, vb.y);
                    mma16816(d0, d1, d2, d3, va0.x, va1.x, va0.y, va1.y, vb.z, vb.w);
                    mma16816(d0, d1, d2, d3, va0.z, va1.z, va0.w, va1.w, vb.x, vb.y);
                }
            }

            // shfl-split + STS chunk c+1 into the other buffer
            if (c + 1 < NCHUNK) {
                uint32_t* nbuf = sA + ((c + 1) & 1) * ABUF_WORDS;
                #pragma unroll
                for (int i = 0; i < 8; i++) {
                    const float x1 = __shfl_xor_sync(0xffffffffu, f[i], 1);
                    if (even) {
                        const int idx = tid + i * 1024;
                        const int r   = idx >> 5;
                        const int w   = (idx & 31) >> 1;
                        uint32_t hi, lo;
                        split2(f[i], x1, hi, lo);
                        const int p = r * PA + frag_pos(w);
                        nbuf[p]     = hi;
                        nbuf[p + 2] = lo;
                    }
                }
            }
        }

        // store D (each warp owns an 8-col half of its 16 rows)
        const int rg0 = row0 + srow0;
        const int rg1 = rg0 + 8;
        if (rg0 < n_nodes)
            *(float2*)(g_xw1 + (size_t)rg0 * HID + h * 8 + q2) = make_float2(d0, d1);
        if (rg1 < n_nodes)
            *(float2*)(g_xw1 + (size_t)rg1 * HID + h * 8 + q2) = make_float2(d2, d3);

        __syncthreads();   // all reads of buffers done before next tile's prologue
    }
}

// ---------------------------------------------------------------------------
__global__ __launch_bounds__(256) void spmm1_gather_kernel(int n_nodes)
{
    const int warp_id = (blockIdx.x * blockDim.x + threadIdx.x) >> 5;
    if (warp_id >= n_nodes) return;
    const int lane = threadIdx.x & 31;
    const int g  = lane >> 2;
    const int j4 = lane & 3;

    const int start = g_rowptr[warp_id];
    const int end   = g_rowptr[warp_id + 1];

    float4 acc = make_float4(0.f, 0.f, 0.f, 0.f);
    for (int e = start + g; e < end; e += 8) {
        const int2 ev = __ldg(&g_csr[e]);
        const float v = __int_as_float(ev.y);
        const float4 x = __ldg((const float4*)(g_xw1 + (size_t)ev.x * HID) + j4);
        acc.x += v * x.x; acc.y += v * x.y; acc.z += v * x.z; acc.w += v * x.w;
    }
    #pragma unroll
    for (int off = 16; off >= 4; off >>= 1) {
        acc.x += __shfl_xor_sync(0xffffffffu, acc.x, off);
        acc.y += __shfl_xor_sync(0xffffffffu, acc.y, off);
        acc.z += __shfl_xor_sync(0xffffffffu, acc.z, off);
        acc.w += __shfl_xor_sync(0xffffffffu, acc.w, off);
    }
    if (g == 0)
        ((float4*)(g_h + (size_t)warp_id * HID))[j4] = acc;
}

// ---------------------------------------------------------------------------
__global__ __launch_bounds__(256) void gemm2_kernel(
    const float* __restrict__ b1,
    const float* __restrict__ W2,
    int n_nodes)
{
    __shared__ float sW2[HID * OUTD];
    __shared__ float sb1[HID];
    if (threadIdx.x < HID * OUTD) sW2[threadIdx.x] = W2[threadIdx.x];
    if (threadIdx.x < HID)        sb1[threadIdx.x] = b1[threadIdx.x];
    __syncthreads();

    int i = blockIdx.x * blockDim.x + threadIdx.x;
    if (i >= n_nodes) return;

    float h[HID];
    const float4* hp = (const float4*)(g_h + (size_t)i * HID);
    #pragma unroll
    for (int q = 0; q < 4; q++) {
        float4 a = hp[q];
        h[4 * q + 0] = a.x; h[4 * q + 1] = a.y;
        h[4 * q + 2] = a.z; h[4 * q + 3] = a.w;
    }

    float o[OUTD];
    #pragma unroll
    for (int j = 0; j < OUTD; j++) o[j] = 0.0f;
    #pragma unroll
    for (int k = 0; k < HID; k++) {
        const float hv = fmaxf(h[k] + sb1[k], 0.0f);
        #pragma unroll
        for (int j = 0; j < OUTD; j++) o[j] += hv * sW2[k * OUTD + j];
    }

    float4* gp = (float4*)(g_g + (size_t)i * 8);
    gp[0] = make_float4(o[0], o[1], o[2], o[3]);
    gp[1] = make_float4(o[4], o[5], o[6], 0.0f);
}

// ---------------------------------------------------------------------------
__global__ __launch_bounds__(256) void spmm2_gather_kernel(
    float* __restrict__ out, const float* __restrict__ b2, int n_nodes)
{
    const int warp_id = (blockIdx.x * blockDim.x + threadIdx.x) >> 5;
    if (warp_id >= n_nodes) return;
    const int lane = threadIdx.x & 31;
    const int g  = lane >> 1;
    const int j4 = lane & 1;

    const int start = g_rowptr[warp_id];
    const int end   = g_rowptr[warp_id + 1];

    float4 acc = make_float4(0.f, 0.f, 0.f, 0.f);
    for (int e = start + g; e < end; e += 16) {
        const int2 ev = __ldg(&g_csr[e]);
        const float v = __int_as_float(ev.y);
        const float4 x = __ldg((const float4*)(g_g + (size_t)ev.x * 8) + j4);
        acc.x += v * x.x; acc.y += v * x.y; acc.z += v * x.z; acc.w += v * x.w;
    }
    #pragma unroll
    for (int off = 16; off >= 2; off >>= 1) {
        acc.x += __shfl_xor_sync(0xffffffffu, acc.x, off);
        acc.y += __shfl_xor_sync(0xffffffffu, acc.y, off);
        acc.z += __shfl_xor_sync(0xffffffffu, acc.z, off);
        acc.w += __shfl_xor_sync(0xffffffffu, acc.w, off);
    }
    float* o = out + (size_t)warp_id * OUTD;
    if (lane == 0) {
        o[0] = acc.x + __ldg(b2 + 0);
        o[1] = acc.y + __ldg(b2 + 1);
        o[2] = acc.z + __ldg(b2 + 2);
        o[3] = acc.w + __ldg(b2 + 3);
    } else if (lane == 1) {
        o[4] = acc.x + __ldg(b2 + 4);
        o[5] = acc.y + __ldg(b2 + 5);
        o[6] = acc.z + __ldg(b2 + 6);
    }
}

// ---------------------------------------------------------------------------
extern "C" void kernel_launch(void* const* d_in, const int* in_sizes, int n_in,
                              void* d_out, int out_size)
{
    const void*  adj     = d_in[0];
    const float* vals    = (const float*)d_in[1];
    const float* feature = (const float*)d_in[2];
    const float* W1      = (const float*)d_in[3];
    const float* b1      = (const float*)d_in[4];
    const float* W2      = (const float*)d_in[5];
    const float* b2      = (const float*)d_in[6];
    float*       out     = (float*)d_out;

    const int n_edges   = in_sizes[1];
    const int n_nodes   = in_sizes[2] / IN_DIM;
    const int ntiles256 = (n_nodes + 255) / 256;
    const int nb        = (n_nodes + 1023) / 1024;

    static cudaStream_t s2 = nullptr;
    static cudaEvent_t ev_fork = nullptr, ev_join = nullptr;
    static int n_sms = 148;
    if (!s2) {
        cudaFuncSetAttribute(gemm1_mma_kernel,
                             cudaFuncAttributeMaxDynamicSharedMemorySize, SMEM_TOTAL);
        cudaStreamCreateWithFlags(&s2, cudaStreamNonBlocking);
        cudaEventCreateWithFlags(&ev_fork, cudaEventDisableTiming);
        cudaEventCreateWithFlags(&ev_join, cudaEventDisableTiming);
        int dev = 0;
        cudaGetDevice(&dev);
        cudaDeviceGetAttribute(&n_sms, cudaDevAttrMultiProcessorCount, dev);
    }

    cudaEventRecord(ev_fork, 0);
    cudaStreamWaitEvent(s2, ev_fork, 0);

    // CSR chain on side stream; gemm1 stays the 4th launch (profiled slot).
    detect_idx_kernel<<<1, 1024, 0, s2>>>((const unsigned int*)adj, n_edges);
    zero_counts_kernel<<<nb, 1024, 0, s2>>>(n_nodes);
    histogram_kernel<<<(n_edges + 255) / 256, 256, 0, s2>>>(adj, n_edges);

    gemm1_mma_kernel<<<n_sms, 1024, SMEM_TOTAL>>>(feature, W1, n_nodes, ntiles256);

    scan1_kernel<<<nb, 1024, 0, s2>>>(n_nodes);
    scan2_kernel<<<1, 256, 0, s2>>>(nb);
    scan3_kernel<<<nb, 1024, 0, s2>>>(n_nodes);
    scatter_kernel<<<(n_edges + 255) / 256, 256, 0, s2>>>(adj, vals, n_edges);
    cudaEventRecord(ev_join, s2);

    cudaStreamWaitEvent(0, ev_join, 0);
    spmm1_gather_kernel<<<(n_nodes * 32 + 255) / 256, 256>>>(n_nodes);
    gemm2_kernel<<<(n_nodes + 255) / 256, 256>>>(b1, W2, n_nodes);
    spmm2_gather_kernel<<<(n_nodes * 32 + 255) / 256, 256>>>(out, b2, n_nodes);
}

// round 15
// speedup vs baseline: 1.4118x; 1.2087x over previous
#include <cuda_runtime.h>
#include <cstdint>

#define IN_DIM 1433
#define HID 16
#define OUTD 7
#define MAXN 200000
#define MAXE 6400000
#define MAXNB 256

// gemm1 mma.sync tiling (R12 layout, k-step-split warps)
#define KP 1448                  // B smem pitch (bf16) -> 724 words, conflict-free
#define KPW (KP / 2)
#define SMEM_BHALF (16 * KP * 2)             // 46336
#define SMEM_B_BYTES (2 * SMEM_BHALF)        // 92672
#define NCHUNK 45                             // 45*32 = 1440 >= 1433
#define CHUNKK 32
#define APITCH 36                             // fp32 pitch (R12, proven)
#define ABUF_FLOATS (256 * APITCH)
#define SMEM_A_BYTES (2 * ABUF_FLOATS * 4)    // 73728
#define SMEM_TOTAL (SMEM_B_BYTES + SMEM_A_BYTES)   // 166400

// Scratch (__device__ globals; allocations are forbidden)
__device__ float g_xw1[(size_t)MAXN * HID];
__device__ float g_h[(size_t)MAXN * HID];
__device__ float g_g[(size_t)MAXN * 8];
__device__ int2  g_csr[(size_t)MAXE];
__device__ int   g_rowcnt[MAXN];
__device__ int   g_rowfill[MAXN];
__device__ int   g_rowptr[MAXN + 1];
__device__ int   g_blocksum[MAXNB];
__device__ int   g_blockoff[MAXNB];
__device__ int   g_idx64;

// ---------------------------------------------------------------------------
__device__ __forceinline__ void split2(float x0, float x1, uint32_t& hi, uint32_t& lo)
{
    uint32_t u0 = __float_as_uint(x0) & 0xFFFF0000u;
    uint32_t u1 = __float_as_uint(x1) & 0xFFFF0000u;
    hi = __byte_perm(u0, u1, 0x7632);
    float l0 = x0 - __uint_as_float(u0);
    float l1 = x1 - __uint_as_float(u1);
    asm("cvt.rn.bf16x2.f32 %0, %1, %2;" : "=r"(lo) : "f"(l1), "f"(l0));
}

__device__ __forceinline__ void mma16816(float& d0, float& d1, float& d2, float& d3,
                                         uint32_t a0, uint32_t a1, uint32_t a2, uint32_t a3,
                                         uint32_t b0, uint32_t b1)
{
    asm volatile(
        "mma.sync.aligned.m16n8k16.row.col.f32.bf16.bf16.f32 "
        "{%0,%1,%2,%3}, {%4,%5,%6,%7}, {%8,%9}, {%0,%1,%2,%3};"
        : "+f"(d0), "+f"(d1), "+f"(d2), "+f"(d3)
        : "r"(a0), "r"(a1), "r"(a2), "r"(a3), "r"(b0), "r"(b1));
}

// ---------------------------------------------------------------------------
__global__ void detect_idx_kernel(const unsigned int* __restrict__ adj_words, int n_edges)
{
    int i = threadIdx.x;
    int samples = n_edges < 1024 ? n_edges : 1024;
    int ok = 1;
    if (i < samples) ok = (adj_words[2 * i + 1] == 0u) ? 1 : 0;
    int all = __syncthreads_and(ok);
    if (i == 0) g_idx64 = all;
}

__device__ __forceinline__ int load_row(const void* adj, int e, int is64) {
    return is64 ? (int)__ldg((const long long*)adj + e)
                : __ldg((const int*)adj + e);
}
__device__ __forceinline__ int load_col(const void* adj, int e, int n_edges, int is64) {
    return is64 ? (int)__ldg((const long long*)adj + (size_t)n_edges + e)
                : __ldg((const int*)adj + (size_t)n_edges + e);
}

// ---------------------------------------------------------------------------
__global__ void zero_counts_kernel(int n)
{
    int i = blockIdx.x * blockDim.x + threadIdx.x;
    if (i < n) { g_rowcnt[i] = 0; g_rowfill[i] = 0; }
}

__global__ __launch_bounds__(256) void histogram_kernel(
    const void* __restrict__ adj, int n_edges)
{
    int e = blockIdx.x * blockDim.x + threadIdx.x;
    if (e >= n_edges) return;
    int r = load_row(adj, e, g_idx64);
    atomicAdd(&g_rowcnt[r], 1);
}

__device__ __forceinline__ int block_excl_scan(int v, int* warp_sums, int nwarps)
{
    const int lane = threadIdx.x & 31, w = threadIdx.x >> 5;
    int x = v;
    #pragma unroll
    for (int off = 1; off < 32; off <<= 1) {
        int y = __shfl_up_sync(0xffffffffu, x, off);
        if (lane >= off) x += y;
    }
    if (lane == 31) warp_sums[w] = x;
    __syncthreads();
    if (w == 0) {
        int s = (lane < nwarps) ? warp_sums[lane] : 0;
        #pragma unroll
        for (int off = 1; off < 32; off <<= 1) {
            int y = __shfl_up_sync(0xffffffffu, s, off);
            if (lane >= off) s += y;
        }
        if (lane < nwarps) warp_sums[lane] = s;
    }
    __syncthreads();
    int base = (w > 0) ? warp_sums[w - 1] : 0;
    return base + x - v;
}

__global__ __launch_bounds__(1024) void scan1_kernel(int n)
{
    __shared__ int ws[32];
    int i = blockIdx.x * 1024 + threadIdx.x;
    int v = (i < n) ? g_rowcnt[i] : 0;
    int ex = block_excl_scan(v, ws, 32);
    if (threadIdx.x == 1023) g_blocksum[blockIdx.x] = ex + v;
}

__global__ __launch_bounds__(256) void scan2_kernel(int nb)
{
    __shared__ int ws[32];
    int i = threadIdx.x;
    int v = (i < nb) ? g_blocksum[i] : 0;
    int ex = block_excl_scan(v, ws, 8);
    if (i < nb) g_blockoff[i] = ex;
}

__global__ __launch_bounds__(1024) void scan3_kernel(int n)
{
    __shared__ int ws[32];
    int i = blockIdx.x * 1024 + threadIdx.x;
    int v = (i < n) ? g_rowcnt[i] : 0;
    int ex = block_excl_scan(v, ws, 32);
    int base = g_blockoff[blockIdx.x];
    if (i < n)      g_rowptr[i] = base + ex;
    if (i == n - 1) g_rowptr[n] = base + ex + v;
}

__global__ __launch_bounds__(256) void scatter_kernel(
    const void* __restrict__ adj, const float* __restrict__ vals, int n_edges)
{
    int e = blockIdx.x * blockDim.x + threadIdx.x;
    if (e >= n_edges) return;
    const int is64 = g_idx64;
    int r = load_row(adj, e, is64);
    int c = load_col(adj, e, n_edges, is64);
    float v = __ldg(vals + e);
    int pos = g_rowptr[r] + atomicAdd(&g_rowfill[r], 1);
    g_csr[pos] = make_int2(c, __float_as_int(v));
}

// ---------------------------------------------------------------------------
// GEMM1 via mma.sync bf16 split (hh + hl + lh).
// 1024 threads = 32 warps. Warps w and w+16 share the same 16 A-rows; warp w
// computes EVEN k-steps, warp w+16 ODD k-steps, each over the full n=16
// (6 MMAs/k-step). Partial sums combined through smem once per tile.
// Memory patterns identical to the proven R12 config.
__global__ __launch_bounds__(1024) void gemm1_mma_kernel(
    const float* __restrict__ feature,
    const float* __restrict__ W1,
    int n_nodes, int ntiles256)
{
    extern __shared__ char smem[];
    uint32_t* shi = (uint32_t*)smem;
    uint32_t* slo = (uint32_t*)(smem + SMEM_BHALF);
    float*    sA  = (float*)(smem + SMEM_B_BYTES);   // [2][256][APITCH]

    const int tid  = threadIdx.x;
    const int warp = tid >> 5;
    const int lane = tid & 31;
    const int g    = lane >> 2;
    const int q    = lane & 3;
    const int q2   = q * 2;
    const int p    = warp >> 4;          // k-step parity owned by this warp
    const int wrow = warp & 15;          // A row-group

    // stage W1^T split (zero-padded to KP)
    for (int idx = tid; idx < 16 * KPW; idx += 1024) {
        int n  = idx / KPW;
        int kp = idx - n * KPW;
        int k  = kp * 2;
        float w0 = (k     < IN_DIM) ? __ldg(W1 + (size_t)k       * HID + n) : 0.0f;
        float w1 = (k + 1 < IN_DIM) ? __ldg(W1 + (size_t)(k + 1) * HID + n) : 0.0f;
        uint32_t hi, lo;
        split2(w0, w1, hi, lo);
        shi[n * KPW + kp] = hi;
        slo[n * KPW + kp] = lo;
    }
    __syncthreads();

    const int srow0 = wrow * 16 + g;
    const int kk    = p * 16;            // k-offset within chunk for this warp

    for (int t = blockIdx.x; t < ntiles256; t += gridDim.x) {
        const int row0 = t * 256;

        float d[2][4];
        #pragma unroll
        for (int h = 0; h < 2; h++)
            #pragma unroll
            for (int j = 0; j < 4; j++) d[h][j] = 0.0f;
        float st[8];

        // prologue: stage chunk 0 (coalesced stride-4B LDG, proven pattern)
        #pragma unroll
        for (int i = 0; i < 8; i++) {
            const int idx = tid + i * 1024;
            const int r   = idx >> 5;
            const int col = idx & 31;
            const int gr  = row0 + r;
            st[i] = (gr < n_nodes && col < IN_DIM)
                  ? __ldg(feature + (size_t)gr * IN_DIM + col) : 0.0f;
        }
        #pragma unroll
        for (int i = 0; i < 8; i++) {
            const int idx = tid + i * 1024;
            sA[(idx >> 5) * APITCH + (idx & 31)] = st[i];
        }

        #pragma unroll 1
        for (int c = 0; c < NCHUNK; c++) {
            __syncthreads();   // publish chunk c; retire readers of chunk c-1

            // LDG chunk c+1 (overlaps compute below)
            if (c + 1 < NCHUNK) {
                const int kc = (c + 1) * CHUNKK;
                #pragma unroll
                for (int i = 0; i < 8; i++) {
                    const int idx = tid + i * 1024;
                    const int r   = idx >> 5;
                    const int col = kc + (idx & 31);
                    const int gr  = row0 + r;
                    st[i] = (gr < n_nodes && col < IN_DIM)
                          ? __ldg(feature + (size_t)gr * IN_DIM + col) : 0.0f;
                }
            }

            // compute this warp's k-step of chunk c (full n=16)
            {
                const float* buf = sA + (c & 1) * ABUF_FLOATS;
                const float2 v0 = *(const float2*)(buf + srow0 * APITCH + kk + q2);
                const float2 v2 = *(const float2*)(buf + srow0 * APITCH + kk + q2 + 8);
                const float2 v1 = *(const float2*)(buf + (srow0 + 8) * APITCH + kk + q2);
                const float2 v3 = *(const float2*)(buf + (srow0 + 8) * APITCH + kk + q2 + 8);

                uint32_t a0h, a0l, a1h, a1l, a2h, a2l, a3h, a3l;
                split2(v0.x, v0.y, a0h, a0l);
                split2(v2.x, v2.y, a2h, a2l);
                split2(v1.x, v1.y, a1h, a1l);
                split2(v3.x, v3.y, a3h, a3l);

                const int kbase = c * 16 + p * 8 + q;
                #pragma unroll
                for (int h = 0; h < 2; h++) {
                    const int base = (h * 8 + g) * KPW + kbase;
                    const uint32_t b0h = shi[base], b1h = shi[base + 4];
                    const uint32_t b0l = slo[base], b1l = slo[base + 4];
                    mma16816(d[h][0], d[h][1], d[h][2], d[h][3],
                             a0h, a1h, a2h, a3h, b0h, b1h);
                    mma16816(d[h][0], d[h][1], d[h][2], d[h][3],
                             a0h, a1h, a2h, a3h, b0l, b1l);
                    mma16816(d[h][0], d[h][1], d[h][2], d[h][3],
                             a0l, a1l, a2l, a3l, b0h, b1h);
                }
            }

            // STS chunk c+1 into the other buffer
            if (c + 1 < NCHUNK) {
                float* nbuf = sA + ((c + 1) & 1) * ABUF_FLOATS;
                #pragma unroll
                for (int i = 0; i < 8; i++) {
                    const int idx = tid + i * 1024;
                    nbuf[(idx >> 5) * APITCH + (idx & 31)] = st[i];
                }
            }
        }

        // --- combine even/odd k-step partials (scratch reuses A buffers) ---
        __syncthreads();                 // all compute done; buffers free
        float* sc = sA;                  // 16 KB scratch
        if (p == 1) {
            float* s = sc + ((size_t)wrow * 32 + lane) * 8;
            #pragma unroll
            for (int h = 0; h < 2; h++)
                #pragma unroll
                for (int j = 0; j < 4; j++) s[h * 4 + j] = d[h][j];
        }
        __syncthreads();
        if (p == 0) {
            const float* s = sc + ((size_t)wrow * 32 + lane) * 8;
            #pragma unroll
            for (int h = 0; h < 2; h++)
                #pragma unroll
                for (int j = 0; j < 4; j++) d[h][j] += s[h * 4 + j];

            const int rg0 = row0 + srow0;
            const int rg1 = rg0 + 8;
            if (rg0 < n_nodes) {
                float* o = g_xw1 + (size_t)rg0 * HID;
                *(float2*)(o + q2)     = make_float2(d[0][0], d[0][1]);
                *(float2*)(o + 8 + q2) = make_float2(d[1][0], d[1][1]);
            }
            if (rg1 < n_nodes) {
                float* o = g_xw1 + (size_t)rg1 * HID;
                *(float2*)(o + q2)     = make_float2(d[0][2], d[0][3]);
                *(float2*)(o + 8 + q2) = make_float2(d[1][2], d[1][3]);
            }
        }
        __syncthreads();                 // scratch reads done before next tile
    }
}

// ---------------------------------------------------------------------------
__global__ __launch_bounds__(256) void spmm1_gather_kernel(int n_nodes)
{
    const int warp_id = (blockIdx.x * blockDim.x + threadIdx.x) >> 5;
    if (warp_id >= n_nodes) return;
    const int lane = threadIdx.x & 31;
    const int g  = lane >> 2;
    const int j4 = lane & 3;

    const int start = g_rowptr[warp_id];
    const int end   = g_rowptr[warp_id + 1];

    float4 acc = make_float4(0.f, 0.f, 0.f, 0.f);
    for (int e = start + g; e < end; e += 8) {
        const int2 ev = __ldg(&g_csr[e]);
        const float v = __int_as_float(ev.y);
        const float4 x = __ldg((const float4*)(g_xw1 + (size_t)ev.x * HID) + j4);
        acc.x += v * x.x; acc.y += v * x.y; acc.z += v * x.z; acc.w += v * x.w;
    }
    #pragma unroll
    for (int off = 16; off >= 4; off >>= 1) {
        acc.x += __shfl_xor_sync(0xffffffffu, acc.x, off);
        acc.y += __shfl_xor_sync(0xffffffffu, acc.y, off);
        acc.z += __shfl_xor_sync(0xffffffffu, acc.z, off);
        acc.w += __shfl_xor_sync(0xffffffffu, acc.w, off);
    }
    if (g == 0)
        ((float4*)(g_h + (size_t)warp_id * HID))[j4] = acc;
}

// ---------------------------------------------------------------------------
__global__ __launch_bounds__(256) void gemm2_kernel(
    const float* __restrict__ b1,
    const float* __restrict__ W2,
    int n_nodes)
{
    __shared__ float sW2[HID * OUTD];
    __shared__ float sb1[HID];
    if (threadIdx.x < HID * OUTD) sW2[threadIdx.x] = W2[threadIdx.x];
    if (threadIdx.x < HID)        sb1[threadIdx.x] = b1[threadIdx.x];
    __syncthreads();

    int i = blockIdx.x * blockDim.x + threadIdx.x;
    if (i >= n_nodes) return;

    float h[HID];
    const float4* hp = (const float4*)(g_h + (size_t)i * HID);
    #pragma unroll
    for (int q = 0; q < 4; q++) {
        float4 a = hp[q];
        h[4 * q + 0] = a.x; h[4 * q + 1] = a.y;
        h[4 * q + 2] = a.z; h[4 * q + 3] = a.w;
    }

    float o[OUTD];
    #pragma unroll
    for (int j = 0; j < OUTD; j++) o[j] = 0.0f;
    #pragma unroll
    for (int k = 0; k < HID; k++) {
        const float hv = fmaxf(h[k] + sb1[k], 0.0f);
        #pragma unroll
        for (int j = 0; j < OUTD; j++) o[j] += hv * sW2[k * OUTD + j];
    }

    float4* gp = (float4*)(g_g + (size_t)i * 8);
    gp[0] = make_float4(o[0], o[1], o[2], o[3]);
    gp[1] = make_float4(o[4], o[5], o[6], 0.0f);
}

// ---------------------------------------------------------------------------
__global__ __launch_bounds__(256) void spmm2_gather_kernel(
    float* __restrict__ out, const float* __restrict__ b2, int n_nodes)
{
    const int warp_id = (blockIdx.x * blockDim.x + threadIdx.x) >> 5;
    if (warp_id >= n_nodes) return;
    const int lane = threadIdx.x & 31;
    const int g  = lane >> 1;
    const int j4 = lane & 1;

    const int start = g_rowptr[warp_id];
    const int end   = g_rowptr[warp_id + 1];

    float4 acc = make_float4(0.f, 0.f, 0.f, 0.f);
    for (int e = start + g; e < end; e += 16) {
        const int2 ev = __ldg(&g_csr[e]);
        const float v = __int_as_float(ev.y);
        const float4 x = __ldg((const float4*)(g_g + (size_t)ev.x * 8) + j4);
        acc.x += v * x.x; acc.y += v * x.y; acc.z += v * x.z; acc.w += v * x.w;
    }
    #pragma unroll
    for (int off = 16; off >= 2; off >>= 1) {
        acc.x += __shfl_xor_sync(0xffffffffu, acc.x, off);
        acc.y += __shfl_xor_sync(0xffffffffu, acc.y, off);
        acc.z += __shfl_xor_sync(0xffffffffu, acc.z, off);
        acc.w += __shfl_xor_sync(0xffffffffu, acc.w, off);
    }
    float* o = out + (size_t)warp_id * OUTD;
    if (lane == 0) {
        o[0] = acc.x + __ldg(b2 + 0);
        o[1] = acc.y + __ldg(b2 + 1);
        o[2] = acc.z + __ldg(b2 + 2);
        o[3] = acc.w + __ldg(b2 + 3);
    } else if (lane == 1) {
        o[4] = acc.x + __ldg(b2 + 4);
        o[5] = acc.y + __ldg(b2 + 5);
        o[6] = acc.z + __ldg(b2 + 6);
    }
}

// ---------------------------------------------------------------------------
extern "C" void kernel_launch(void* const* d_in, const int* in_sizes, int n_in,
                              void* d_out, int out_size)
{
    const void*  adj     = d_in[0];
    const float* vals    = (const float*)d_in[1];
    const float* feature = (const float*)d_in[2];
    const float* W1      = (const float*)d_in[3];
    const float* b1      = (const float*)d_in[4];
    const float* W2      = (const float*)d_in[5];
    const float* b2      = (const float*)d_in[6];
    float*       out     = (float*)d_out;

    const int n_edges   = in_sizes[1];
    const int n_nodes   = in_sizes[2] / IN_DIM;
    const int ntiles256 = (n_nodes + 255) / 256;
    const int nb        = (n_nodes + 1023) / 1024;

    static cudaStream_t s2 = nullptr;
    static cudaEvent_t ev_fork = nullptr, ev_join = nullptr;
    static int n_sms = 148;
    if (!s2) {
        cudaFuncSetAttribute(gemm1_mma_kernel,
                             cudaFuncAttributeMaxDynamicSharedMemorySize, SMEM_TOTAL);
        cudaStreamCreateWithFlags(&s2, cudaStreamNonBlocking);
        cudaEventCreateWithFlags(&ev_fork, cudaEventDisableTiming);
        cudaEventCreateWithFlags(&ev_join, cudaEventDisableTiming);
        int dev = 0;
        cudaGetDevice(&dev);
        cudaDeviceGetAttribute(&n_sms, cudaDevAttrMultiProcessorCount, dev);
    }

    cudaEventRecord(ev_fork, 0);
    cudaStreamWaitEvent(s2, ev_fork, 0);

    // CSR chain on side stream; gemm1 stays the 4th launch (profiled slot).
    detect_idx_kernel<<<1, 1024, 0, s2>>>((const unsigned int*)adj, n_edges);
    zero_counts_kernel<<<nb, 1024, 0, s2>>>(n_nodes);
    histogram_kernel<<<(n_edges + 255) / 256, 256, 0, s2>>>(adj, n_edges);

    gemm1_mma_kernel<<<n_sms, 1024, SMEM_TOTAL>>>(feature, W1, n_nodes, ntiles256);

    scan1_kernel<<<nb, 1024, 0, s2>>>(n_nodes);
    scan2_kernel<<<1, 256, 0, s2>>>(nb);
    scan3_kernel<<<nb, 1024, 0, s2>>>(n_nodes);
    scatter_kernel<<<(n_edges + 255) / 256, 256, 0, s2>>>(adj, vals, n_edges);
    cudaEventRecord(ev_join, s2);

    cudaStreamWaitEvent(0, ev_join, 0);
    spmm1_gather_kernel<<<(n_nodes * 32 + 255) / 256, 256>>>(n_nodes);
    gemm2_kernel<<<(n_nodes + 255) / 256, 256>>>(b1, W2, n_nodes);
    spmm2_gather_kernel<<<(n_nodes * 32 + 255) / 256, 256>>>(out, b2, n_nodes);
}